// round 2
// baseline (speedup 1.0000x reference)
#include <cuda_runtime.h>

// Problem constants
#define BB   4
#define SEQ  4096
#define DIM  128
#define KD   64
#define VD   128

#define TQ   128            // q tile
#define TJ   128            // j tile
#define NQT  (SEQ / TQ)     // 32
#define NJT  (SEQ / TJ)     // 32
#define SC_QCHUNK 8         // q-tiles per k_scores CTA
#define N_SCHUNK  4         // ceil(32/8)
#define OUT_JCHUNK 4        // j-tiles per k_out CTA
#define N_OCHUNK   8        // ceil(32/4)

// ---------------- scratch (static __device__ — allocation-free) ----------------
__device__ float  g_Q[BB * SEQ * KD];                    // 4 MB
__device__ float  g_K[BB * SEQ * KD];                    // 4 MB
__device__ float  g_V[BB * SEQ * VD];                    // 8 MB
__device__ float  g_S[(size_t)BB * SEQ * SEQ];           // 268 MB, layout [b][j][q]
__device__ float2 g_ml[N_SCHUNK][BB][SEQ];               // per-chunk (m, l)
__device__ float  g_c[BB][SEQ];                          // m + log(l)
__device__ float  g_Opart[N_OCHUNK][BB][SEQ][VD];        // 67 MB partial outputs

// =========================== projections ===========================
// GEMM [16384 x 128] @ [128 x 256] -> Q|K|V. Grid (128 row-tiles, 2 col-tiles).
__global__ __launch_bounds__(256, 1) void k_proj(
    const float* __restrict__ x,
    const float* __restrict__ Wq, const float* __restrict__ bq,
    const float* __restrict__ Wk, const float* __restrict__ bk,
    const float* __restrict__ Wv, const float* __restrict__ bv)
{
    extern __shared__ float sm[];
    float* xs = sm;              // [128 d][133] transposed, padded
    float* ws = sm + 128 * 133;  // [128 d][133]
    const int tid = threadIdx.x;
    const int tx = tid & 15, ty = tid >> 4;
    const int row0 = blockIdx.x * 128;
    const int col0 = blockIdx.y * 128;

    // x tile: LDG.128, scatter-transpose into smem
    #pragma unroll 4
    for (int i = tid; i < 128 * 32; i += 256) {
        int r = i >> 5, c4 = (i & 31) * 4;
        float4 v = *(const float4*)&x[(size_t)(row0 + r) * 128 + c4];
        xs[(c4 + 0) * 133 + r] = v.x;
        xs[(c4 + 1) * 133 + r] = v.y;
        xs[(c4 + 2) * 133 + r] = v.z;
        xs[(c4 + 3) * 133 + r] = v.w;
    }
    // W tile (col-blocked concat of Wq|Wk|Wv rows): LDG.128 along d
    #pragma unroll 4
    for (int i = tid; i < 128 * 32; i += 256) {
        int cl = i >> 5, k4 = (i & 31) * 4;
        int col = col0 + cl;
        float4 w;
        if (col < 64)        w = *(const float4*)&Wq[col * 128 + k4];
        else if (col < 128)  w = *(const float4*)&Wk[(col - 64) * 128 + k4];
        else                 w = *(const float4*)&Wv[(col - 128) * 128 + k4];
        ws[(k4 + 0) * 133 + cl] = w.x;
        ws[(k4 + 1) * 133 + cl] = w.y;
        ws[(k4 + 2) * 133 + cl] = w.z;
        ws[(k4 + 3) * 133 + cl] = w.w;
    }
    __syncthreads();

    float acc[8][8];
    #pragma unroll
    for (int i = 0; i < 8; i++)
        #pragma unroll
        for (int j = 0; j < 8; j++) acc[i][j] = 0.f;

    for (int kk = 0; kk < 128; kk++) {
        float a[8], b[8];
        #pragma unroll
        for (int i = 0; i < 8; i++) a[i] = xs[kk * 133 + ty + 16 * i];
        #pragma unroll
        for (int j = 0; j < 8; j++) b[j] = ws[kk * 133 + tx + 16 * j];
        #pragma unroll
        for (int i = 0; i < 8; i++)
            #pragma unroll
            for (int j = 0; j < 8; j++) acc[i][j] += a[i] * b[j];
    }
    __syncthreads();
    float* st = sm;  // reuse: [128][128]
    #pragma unroll
    for (int i = 0; i < 8; i++)
        #pragma unroll
        for (int j = 0; j < 8; j++)
            st[(ty + 16 * i) * 128 + tx + 16 * j] = acc[i][j];
    __syncthreads();
    // STG.128; 4-col groups never straddle the 64/128 boundaries
    for (int i = tid; i < 128 * 32; i += 256) {
        int r = i >> 5, g = (i & 31) * 4;
        int col = col0 + g;
        int row = row0 + r;
        float4 v = *(float4*)&st[r * 128 + g];
        if (col < 64) {
            v.x += bq[col]; v.y += bq[col + 1]; v.z += bq[col + 2]; v.w += bq[col + 3];
            *(float4*)&g_Q[row * 64 + col] = v;
        } else if (col < 128) {
            int c = col - 64;
            v.x += bk[c]; v.y += bk[c + 1]; v.z += bk[c + 2]; v.w += bk[c + 3];
            *(float4*)&g_K[row * 64 + c] = v;
        } else {
            int c = col - 128;
            v.x += bv[c]; v.y += bv[c + 1]; v.z += bv[c + 2]; v.w += bv[c + 3];
            *(float4*)&g_V[(size_t)row * 128 + c] = v;
        }
    }
}

// =========================== scores + column stats ===========================
// CTA = (jt, qchunk, b). Computes S tiles (scaled, causal-masked with -1e30),
// stores them to g_S[b][j][q], and tracks online per-column (m, l) for the chunk.
__global__ __launch_bounds__(256, 1) void k_scores()
{
    extern __shared__ float sm[];
    float* Qs = sm;                  // [64][133]
    float* Ks = sm + 64 * 133;       // [64][133]
    float* Ss = sm + 2 * 64 * 133;   // [128][129] staging / reduction scratch
    const int tid = threadIdx.x;
    const int tx = tid & 15, ty = tid >> 4;
    const int jt = blockIdx.x;
    const int chunk = blockIdx.y;
    const int b = blockIdx.z;

    int qt0 = jt + chunk * SC_QCHUNK;
    if (qt0 >= NQT) return;
    int qt1 = jt + (chunk + 1) * SC_QCHUNK;
    if (qt1 > NQT) qt1 = NQT;

    const int j0 = jt * TJ;
    const int rowK = b * SEQ + j0;
    #pragma unroll 4
    for (int i = tid; i < 128 * 16; i += 256) {
        int r = i >> 4, c4 = (i & 15) * 4;
        float4 v = *(const float4*)&g_K[(rowK + r) * 64 + c4];
        Ks[(c4 + 0) * 133 + r] = v.x;
        Ks[(c4 + 1) * 133 + r] = v.y;
        Ks[(c4 + 2) * 133 + r] = v.z;
        Ks[(c4 + 3) * 133 + r] = v.w;
    }

    float m[8], l[8];
    #pragma unroll
    for (int j = 0; j < 8; j++) { m[j] = -1e30f; l[j] = 0.f; }

    for (int qt = qt0; qt < qt1; qt++) {
        __syncthreads();  // protects Qs (prev GEMM) and Ss (prev global write)
        const int q0 = qt * TQ;
        const int rowQ = b * SEQ + q0;
        #pragma unroll 4
        for (int i = tid; i < 128 * 16; i += 256) {
            int r = i >> 4, c4 = (i & 15) * 4;
            float4 v = *(const float4*)&g_Q[(rowQ + r) * 64 + c4];
            Qs[(c4 + 0) * 133 + r] = v.x;
            Qs[(c4 + 1) * 133 + r] = v.y;
            Qs[(c4 + 2) * 133 + r] = v.z;
            Qs[(c4 + 3) * 133 + r] = v.w;
        }
        __syncthreads();

        float s[8][8];
        #pragma unroll
        for (int i = 0; i < 8; i++)
            #pragma unroll
            for (int j = 0; j < 8; j++) s[i][j] = 0.f;
        for (int kk = 0; kk < 64; kk++) {
            float a[8], bq8[8];
            #pragma unroll
            for (int i = 0; i < 8; i++) a[i] = Qs[kk * 133 + ty + 16 * i];
            #pragma unroll
            for (int j = 0; j < 8; j++) bq8[j] = Ks[kk * 133 + tx + 16 * j];
            #pragma unroll
            for (int i = 0; i < 8; i++)
                #pragma unroll
                for (int j = 0; j < 8; j++) s[i][j] += a[i] * bq8[j];
        }
        const bool diag = (q0 < j0 + TJ);  // only first tile of the qt range
        #pragma unroll
        for (int i = 0; i < 8; i++)
            #pragma unroll
            for (int j = 0; j < 8; j++) {
                float v = s[i][j] * 0.125f;  // 1/sqrt(64)
                if (diag && (q0 + ty + 16 * i) < (j0 + tx + 16 * j)) v = -1e30f;
                s[i][j] = v;
            }
        // online per-column (m, l); masked (-1e30) contributes 0
        #pragma unroll
        for (int j = 0; j < 8; j++) {
            float tmax = s[0][j];
            #pragma unroll
            for (int i = 1; i < 8; i++) tmax = fmaxf(tmax, s[i][j]);
            if (tmax > m[j]) { l[j] *= __expf(m[j] - tmax); m[j] = tmax; }
            float sum = 0.f;
            #pragma unroll
            for (int i = 0; i < 8; i++) {
                float sv = s[i][j];
                sum += (sv > -1e29f) ? __expf(sv - m[j]) : 0.f;
            }
            l[j] += sum;
        }
        // stage tile [j][q] and stream to g_S with STG.128
        #pragma unroll
        for (int i = 0; i < 8; i++)
            #pragma unroll
            for (int j = 0; j < 8; j++)
                Ss[(tx + 16 * j) * 129 + (ty + 16 * i)] = s[i][j];
        __syncthreads();
        size_t base = ((size_t)b << 24) + (size_t)j0 * SEQ + q0;
        #pragma unroll 4
        for (int i = tid; i < 128 * 32; i += 256) {
            int jr = i >> 5, q4 = (i & 31) * 4;
            const float* r = &Ss[jr * 129 + q4];
            float4 v = make_float4(r[0], r[1], r[2], r[3]);
            *(float4*)&g_S[base + (size_t)jr * SEQ + q4] = v;
        }
    }
    __syncthreads();
    // reduce (m,l) over the 16 ty-threads per column
    float* mb = Ss;             // [16][128]
    float* lb = Ss + 16 * 128;  // [16][128]
    #pragma unroll
    for (int j = 0; j < 8; j++) {
        mb[ty * 128 + tx + 16 * j] = m[j];
        lb[ty * 128 + tx + 16 * j] = l[j];
    }
    __syncthreads();
    if (tid < 128) {
        float M = -1e30f;
        #pragma unroll
        for (int i = 0; i < 16; i++) M = fmaxf(M, mb[i * 128 + tid]);
        float L = 0.f;
        #pragma unroll
        for (int i = 0; i < 16; i++) {
            float mm = mb[i * 128 + tid];
            L += (mm > -1e29f) ? lb[i * 128 + tid] * __expf(mm - M) : 0.f;
        }
        g_ml[chunk][b][j0 + tid] = make_float2(M, L);
    }
}

// =========================== merge chunk stats ===========================
__global__ void k_combine()
{
    int idx = blockIdx.x * 256 + threadIdx.x;
    if (idx >= BB * SEQ) return;
    int b = idx >> 12, j = idx & (SEQ - 1);
    int jt = j >> 7;
    int nc = (NQT - 1 - jt) / SC_QCHUNK + 1;
    float M = -1e30f;
    for (int c = 0; c < nc; c++) M = fmaxf(M, g_ml[c][b][j].x);
    float L = 0.f;
    for (int c = 0; c < nc; c++) {
        float2 p = g_ml[c][b][j];
        L += (p.x > -1e29f) ? p.y * __expf(p.x - M) : 0.f;
    }
    g_c[b][j] = M + logf(L);
}

// =========================== output GEMM ===========================
// CTA = (qt, jchunk, b). O[128q][128v] += exp(S - c_j) @ V over its j-tiles.
__global__ __launch_bounds__(256, 1) void k_out()
{
    extern __shared__ float sm[];
    float* Ps = sm;                  // [128 j][128 q]
    float* Vs = sm + 128 * 128;      // [128 j][128 v]
    const int tid = threadIdx.x;
    const int tx = tid & 15, ty = tid >> 4;
    const int qt = blockIdx.x;
    const int chunk = blockIdx.y;
    const int b = blockIdx.z;

    int jt0 = chunk * OUT_JCHUNK;
    if (jt0 > qt) return;
    int jt1 = jt0 + OUT_JCHUNK - 1;
    if (jt1 > qt) jt1 = qt;
    const int q0 = qt * TQ;

    float acc[8][8];
    #pragma unroll
    for (int i = 0; i < 8; i++)
        #pragma unroll
        for (int j = 0; j < 8; j++) acc[i][j] = 0.f;

    for (int jt = jt0; jt <= jt1; jt++) {
        const int j0 = jt * TJ;
        __syncthreads();  // protect Ps/Vs from previous GEMM reads
        size_t sbase = ((size_t)b << 24) + (size_t)j0 * SEQ + q0;
        #pragma unroll 4
        for (int i = tid; i < 128 * 32; i += 256) {
            int jr = i >> 5, q4 = (i & 31) * 4;
            float4 s = *(const float4*)&g_S[sbase + (size_t)jr * SEQ + q4];
            float c = g_c[b][j0 + jr];
            float4 p = make_float4(__expf(s.x - c), __expf(s.y - c),
                                   __expf(s.z - c), __expf(s.w - c));
            *(float4*)&Ps[jr * 128 + q4] = p;  // masked (-1e30) -> 0
        }
        #pragma unroll 4
        for (int i = tid; i < 128 * 32; i += 256) {
            int jr = i >> 5, v4 = (i & 31) * 4;
            *(float4*)&Vs[jr * 128 + v4] =
                *(const float4*)&g_V[(size_t)(b * SEQ + j0 + jr) * 128 + v4];
        }
        __syncthreads();
        for (int kk = 0; kk < 128; kk++) {
            float a[8], v8[8];
            #pragma unroll
            for (int i = 0; i < 8; i++) a[i] = Ps[kk * 128 + ty + 16 * i];
            #pragma unroll
            for (int j = 0; j < 8; j++) v8[j] = Vs[kk * 128 + tx + 16 * j];
            #pragma unroll
            for (int i = 0; i < 8; i++)
                #pragma unroll
                for (int j = 0; j < 8; j++) acc[i][j] += a[i] * v8[j];
        }
    }
    __syncthreads();
    #pragma unroll
    for (int i = 0; i < 8; i++)
        #pragma unroll
        for (int j = 0; j < 8; j++)
            Ps[(ty + 16 * i) * 128 + tx + 16 * j] = acc[i][j];
    __syncthreads();
    #pragma unroll 4
    for (int i = tid; i < 128 * 32; i += 256) {
        int r = i >> 5, v4 = (i & 31) * 4;
        *(float4*)&g_Opart[chunk][b][q0 + r][v4] = *(float4*)&Ps[r * 128 + v4];
    }
}

// =========================== reduce partials + concat(x, attn) ===========================
__global__ void k_reduce(const float* __restrict__ x, float* __restrict__ out)
{
    int idx = blockIdx.x * 256 + threadIdx.x;   // one float4 per thread
    if (idx >= BB * SEQ * 64) return;
    int c4 = (idx & 63) * 4;
    int row = idx >> 6;           // b*SEQ + s
    int s = row & (SEQ - 1);
    int b = row >> 12;
    float4 v;
    if (c4 < 128) {
        v = *(const float4*)&x[(size_t)row * 128 + c4];
    } else {
        int vc = c4 - 128;
        int nc = (s >> 7) / OUT_JCHUNK + 1;
        v = make_float4(0.f, 0.f, 0.f, 0.f);
        for (int c = 0; c < nc; c++) {
            float4 p = *(const float4*)&g_Opart[c][b][s][vc];
            v.x += p.x; v.y += p.y; v.z += p.z; v.w += p.w;
        }
    }
    *(float4*)&out[(size_t)row * 256 + c4] = v;
}

// =========================== launch ===========================
extern "C" void kernel_launch(void* const* d_in, const int* in_sizes, int n_in,
                              void* d_out, int out_size)
{
    const float* x  = (const float*)d_in[0];
    const float* Wq = (const float*)d_in[1];
    const float* bq = (const float*)d_in[2];
    const float* Wk = (const float*)d_in[3];
    const float* bk = (const float*)d_in[4];
    const float* Wv = (const float*)d_in[5];
    const float* bv = (const float*)d_in[6];
    float* out = (float*)d_out;

    const int SM_PROJ = (128 * 133 * 2) * 4;                 // 136192
    const int SM_SC   = (64 * 133 * 2 + 128 * 129) * 4;      // 134144
    const int SM_OUT  = (128 * 128 * 2) * 4;                 // 131072

    cudaFuncSetAttribute(k_proj,   cudaFuncAttributeMaxDynamicSharedMemorySize, SM_PROJ);
    cudaFuncSetAttribute(k_scores, cudaFuncAttributeMaxDynamicSharedMemorySize, SM_SC);
    cudaFuncSetAttribute(k_out,    cudaFuncAttributeMaxDynamicSharedMemorySize, SM_OUT);

    k_proj<<<dim3(128, 2), 256, SM_PROJ>>>(x, Wq, bq, Wk, bk, Wv, bv);
    k_scores<<<dim3(NJT, N_SCHUNK, BB), 256, SM_SC>>>();
    k_combine<<<(BB * SEQ + 255) / 256, 256>>>();
    k_out<<<dim3(NQT, N_OCHUNK, BB), 256, SM_OUT>>>();
    k_reduce<<<(BB * SEQ * 64 + 255) / 256, 256>>>(x, out);
}

// round 5
// speedup vs baseline: 1.7871x; 1.7871x over previous
#include <cuda_runtime.h>
#include <cuda_bf16.h>
#include <cstdint>

#define BB   4
#define SEQ  4096
#define KD   64
#define VD   128
#define NQT  32
#define NJT  32
#define SC_QCHUNK 8
#define N_SCHUNK  4
#define OUT_JCHUNK 4
#define N_OCHUNK   8

// ---------------- device scratch (allocation-free) ----------------
__device__ __align__(16) __nv_bfloat16 g_Qhi[BB * SEQ * KD];
__device__ __align__(16) __nv_bfloat16 g_Qlo[BB * SEQ * KD];
__device__ __align__(16) __nv_bfloat16 g_Khi[BB * SEQ * KD];
__device__ __align__(16) __nv_bfloat16 g_Klo[BB * SEQ * KD];
__device__ __align__(16) __nv_bfloat16 g_Vthi[BB * VD * SEQ];   // [b][v][s]
__device__ __align__(16) __nv_bfloat16 g_Vtlo[BB * VD * SEQ];
__device__ __align__(16) float  g_S[(size_t)BB * SEQ * SEQ];    // [b][q][j]
__device__ float2 g_ml[N_SCHUNK][BB][SEQ];
__device__ float  g_c[BB][SEQ];
__device__ float  g_Opart[N_OCHUNK][BB][SEQ][VD];

// ---------------- helpers ----------------
__device__ __forceinline__ void split_pack(float a, float b, uint32_t& hi, uint32_t& lo) {
    __nv_bfloat16 ah = __float2bfloat16(a), bh = __float2bfloat16(b);
    __nv_bfloat16 al = __float2bfloat16(a - __bfloat162float(ah));
    __nv_bfloat16 bl = __float2bfloat16(b - __bfloat162float(bh));
    hi = ((uint32_t)__bfloat16_as_ushort(bh) << 16) | __bfloat16_as_ushort(ah);
    lo = ((uint32_t)__bfloat16_as_ushort(bl) << 16) | __bfloat16_as_ushort(al);
}

__device__ __forceinline__ void mma16816(float* c, const uint32_t* a, const uint32_t* b) {
    asm volatile("mma.sync.aligned.m16n8k16.row.col.f32.bf16.bf16.f32 "
                 "{%0,%1,%2,%3}, {%4,%5,%6,%7}, {%8,%9}, {%0,%1,%2,%3};"
                 : "+f"(c[0]), "+f"(c[1]), "+f"(c[2]), "+f"(c[3])
                 : "r"(a[0]), "r"(a[1]), "r"(a[2]), "r"(a[3]), "r"(b[0]), "r"(b[1]));
}

// =========================== k_proj (SIMT fp32, emits split operands) ===========================
__global__ __launch_bounds__(256, 1) void k_proj(
    const float* __restrict__ x,
    const float* __restrict__ Wq, const float* __restrict__ bq,
    const float* __restrict__ Wk, const float* __restrict__ bk,
    const float* __restrict__ Wv, const float* __restrict__ bv)
{
    extern __shared__ float sm[];
    float* xs = sm;              // [128 d][133]
    float* ws = sm + 128 * 133;
    const int tid = threadIdx.x, tx = tid & 15, ty = tid >> 4;
    const int row0 = blockIdx.x * 128;
    const int col0 = blockIdx.y * 128;   // 0: Q|K, 128: V

    #pragma unroll 4
    for (int i = tid; i < 128 * 32; i += 256) {
        int r = i >> 5, c4 = (i & 31) * 4;
        float4 v = *(const float4*)&x[(size_t)(row0 + r) * 128 + c4];
        xs[(c4 + 0) * 133 + r] = v.x; xs[(c4 + 1) * 133 + r] = v.y;
        xs[(c4 + 2) * 133 + r] = v.z; xs[(c4 + 3) * 133 + r] = v.w;
    }
    #pragma unroll 4
    for (int i = tid; i < 128 * 32; i += 256) {
        int cl = i >> 5, k4 = (i & 31) * 4;
        int col = col0 + cl;
        float4 w;
        if (col < 64)        w = *(const float4*)&Wq[col * 128 + k4];
        else if (col < 128)  w = *(const float4*)&Wk[(col - 64) * 128 + k4];
        else                 w = *(const float4*)&Wv[(col - 128) * 128 + k4];
        ws[(k4 + 0) * 133 + cl] = w.x; ws[(k4 + 1) * 133 + cl] = w.y;
        ws[(k4 + 2) * 133 + cl] = w.z; ws[(k4 + 3) * 133 + cl] = w.w;
    }
    __syncthreads();

    float acc[8][8];
    #pragma unroll
    for (int i = 0; i < 8; i++)
        #pragma unroll
        for (int j = 0; j < 8; j++) acc[i][j] = 0.f;
    for (int kk = 0; kk < 128; kk++) {
        float a[8], b[8];
        #pragma unroll
        for (int i = 0; i < 8; i++) a[i] = xs[kk * 133 + ty + 16 * i];
        #pragma unroll
        for (int j = 0; j < 8; j++) b[j] = ws[kk * 133 + tx + 16 * j];
        #pragma unroll
        for (int i = 0; i < 8; i++)
            #pragma unroll
            for (int j = 0; j < 8; j++) acc[i][j] += a[i] * b[j];
    }
    __syncthreads();
    float* st = sm;   // reuse: [128][132]
    #pragma unroll
    for (int i = 0; i < 8; i++)
        #pragma unroll
        for (int j = 0; j < 8; j++)
            st[(ty + 16 * i) * 132 + tx + 16 * j] = acc[i][j];
    __syncthreads();

    if (blockIdx.y == 0) {
        for (int i = tid; i < 128 * 64; i += 256) {
            int r = i >> 6, cp = (i & 63) * 2;
            int row = row0 + r;
            float v0 = st[r * 132 + cp], v1 = st[r * 132 + cp + 1];
            uint32_t hi, lo;
            if (cp < 64) {
                v0 = (v0 + bq[cp]) * 0.125f;
                v1 = (v1 + bq[cp + 1]) * 0.125f;
                split_pack(v0, v1, hi, lo);
                *(uint32_t*)&g_Qhi[row * KD + cp] = hi;
                *(uint32_t*)&g_Qlo[row * KD + cp] = lo;
            } else {
                int c = cp - 64;
                v0 += bk[c]; v1 += bk[c + 1];
                split_pack(v0, v1, hi, lo);
                *(uint32_t*)&g_Khi[row * KD + c] = hi;
                *(uint32_t*)&g_Klo[row * KD + c] = lo;
            }
        }
    } else {
        // transpose V block -> g_Vt[b][v][s] bf16 hi/lo
        int bb = row0 >> 12, s0 = row0 & (SEQ - 1);
        int v = tid >> 1, h = tid & 1;
        size_t base = ((size_t)(bb * VD + v)) * SEQ + s0 + h * 64;
        float bias = bv[v];
        #pragma unroll
        for (int k2 = 0; k2 < 8; k2++) {
            uint32_t hw[4], lw[4];
            #pragma unroll
            for (int p = 0; p < 4; p++) {
                int r = h * 64 + k2 * 8 + p * 2;
                float v0 = st[r * 132 + v] + bias;
                float v1 = st[(r + 1) * 132 + v] + bias;
                split_pack(v0, v1, hw[p], lw[p]);
            }
            *(uint4*)&g_Vthi[base + k2 * 8] = make_uint4(hw[0], hw[1], hw[2], hw[3]);
            *(uint4*)&g_Vtlo[base + k2 * 8] = make_uint4(lw[0], lw[1], lw[2], lw[3]);
        }
    }
}

// =========================== k_scores (mma.sync bf16) ===========================
// smem byte offsets: K/Q tiles [128][72] bf16 (conflict-free frag loads), Sst [128][132] f32
#define SCS_KH 0
#define SCS_KL 18432
#define SCS_QH 36864
#define SCS_QL 55296
#define SCS_ST 73728
#define SM_SC  (73728 + 128 * 132 * 4)

__global__ __launch_bounds__(256, 1) void k_scores()
{
    extern __shared__ char smc[];
    __nv_bfloat16* Kh = (__nv_bfloat16*)(smc + SCS_KH);
    __nv_bfloat16* Kl = (__nv_bfloat16*)(smc + SCS_KL);
    __nv_bfloat16* Qh = (__nv_bfloat16*)(smc + SCS_QH);
    __nv_bfloat16* Ql = (__nv_bfloat16*)(smc + SCS_QL);
    float* Sst = (float*)(smc + SCS_ST);

    const int tid = threadIdx.x, lane = tid & 31, w = tid >> 5;
    const int r4 = lane >> 2, c2 = (lane & 3) * 2;
    const int qw = (w & 3) * 32, jw = (w >> 2) * 64;
    const int jt = blockIdx.x, chunk = blockIdx.y, b = blockIdx.z;
    int qt0 = jt + chunk * SC_QCHUNK;
    if (qt0 >= NQT) return;
    int qt1 = min(qt0 + SC_QCHUNK, NQT);
    const int j0 = jt * 128;

    for (int i = tid; i < 128 * 8; i += 256) {
        int r = i >> 3, c8 = (i & 7) * 8;
        *(uint4*)&Kh[r * 72 + c8] = *(const uint4*)&g_Khi[(size_t)(b * SEQ + j0 + r) * KD + c8];
        *(uint4*)&Kl[r * 72 + c8] = *(const uint4*)&g_Klo[(size_t)(b * SEQ + j0 + r) * KD + c8];
    }

    const int jcol = tid & 127, hh = tid >> 7;
    float mreg = -1e30f, lreg = 0.f;

    for (int qt = qt0; qt < qt1; qt++) {
        __syncthreads();   // protect Q/Sst from previous iteration readers
        const int q0 = qt * 128;
        for (int i = tid; i < 128 * 8; i += 256) {
            int r = i >> 3, c8 = (i & 7) * 8;
            *(uint4*)&Qh[r * 72 + c8] = *(const uint4*)&g_Qhi[(size_t)(b * SEQ + q0 + r) * KD + c8];
            *(uint4*)&Ql[r * 72 + c8] = *(const uint4*)&g_Qlo[(size_t)(b * SEQ + q0 + r) * KD + c8];
        }
        __syncthreads();

        float acc[2][8][4];
        #pragma unroll
        for (int mt = 0; mt < 2; mt++)
            #pragma unroll
            for (int nt = 0; nt < 8; nt++)
                #pragma unroll
                for (int e = 0; e < 4; e++) acc[mt][nt][e] = 0.f;

        #pragma unroll
        for (int ks = 0; ks < 4; ks++) {
            const int col = ks * 16 + c2;
            uint32_t bh[8][2], bl[8][2];
            #pragma unroll
            for (int nt = 0; nt < 8; nt++) {
                int n = (jw + nt * 8 + r4) * 72 + col;
                bh[nt][0] = *(uint32_t*)&Kh[n]; bh[nt][1] = *(uint32_t*)&Kh[n + 8];
                bl[nt][0] = *(uint32_t*)&Kl[n]; bl[nt][1] = *(uint32_t*)&Kl[n + 8];
            }
            #pragma unroll
            for (int mt = 0; mt < 2; mt++) {
                int rr = (qw + mt * 16 + r4) * 72 + col;
                uint32_t ah[4], al[4];
                ah[0] = *(uint32_t*)&Qh[rr];     ah[1] = *(uint32_t*)&Qh[rr + 8 * 72];
                ah[2] = *(uint32_t*)&Qh[rr + 8]; ah[3] = *(uint32_t*)&Qh[rr + 8 * 72 + 8];
                al[0] = *(uint32_t*)&Ql[rr];     al[1] = *(uint32_t*)&Ql[rr + 8 * 72];
                al[2] = *(uint32_t*)&Ql[rr + 8]; al[3] = *(uint32_t*)&Ql[rr + 8 * 72 + 8];
                #pragma unroll
                for (int nt = 0; nt < 8; nt++) {
                    mma16816(acc[mt][nt], ah, bh[nt]);
                    mma16816(acc[mt][nt], ah, bl[nt]);
                    mma16816(acc[mt][nt], al, bh[nt]);
                }
            }
        }

        // mask + stage
        const bool diag = (qt == jt);
        #pragma unroll
        for (int mt = 0; mt < 2; mt++)
            #pragma unroll
            for (int nt = 0; nt < 8; nt++) {
                int jl = jw + nt * 8 + c2;
                #pragma unroll
                for (int half = 0; half < 2; half++) {
                    int ql = qw + mt * 16 + r4 + half * 8;
                    float v0 = acc[mt][nt][half * 2], v1 = acc[mt][nt][half * 2 + 1];
                    if (diag) {
                        if (ql < jl) v0 = -1e30f;
                        if (ql < jl + 1) v1 = -1e30f;
                    }
                    *(float2*)&Sst[ql * 132 + jl] = make_float2(v0, v1);
                }
            }
        __syncthreads();
        // store S [b][q][j] coalesced
        size_t base = ((size_t)(b * SEQ + q0)) * SEQ + j0;
        for (int i = tid; i < 128 * 32; i += 256) {
            int qq = i >> 5, f = (i & 31) * 4;
            *(float4*)&g_S[base + (size_t)qq * SEQ + f] = *(float4*)&Sst[qq * 132 + f];
        }
        // online column stats over q
        float tm = -1e30f;
        #pragma unroll 8
        for (int qq = hh * 64; qq < hh * 64 + 64; qq++) tm = fmaxf(tm, Sst[qq * 132 + jcol]);
        if (tm > mreg) { lreg *= __expf(mreg - tm); mreg = tm; }
        float ssum = 0.f;
        #pragma unroll 8
        for (int qq = hh * 64; qq < hh * 64 + 64; qq++) {
            float v = Sst[qq * 132 + jcol];
            ssum += (v > -1e29f) ? __expf(v - mreg) : 0.f;
        }
        lreg += ssum;
    }
    __syncthreads();
    float* mb2 = Sst; float* lb2 = Sst + 256;
    mb2[hh * 128 + jcol] = mreg; lb2[hh * 128 + jcol] = lreg;
    __syncthreads();
    if (tid < 128) {
        float m0 = mb2[tid], m1 = mb2[128 + tid], l0 = lb2[tid], l1 = lb2[128 + tid];
        float M = fmaxf(m0, m1);
        float L = ((m0 > -1e29f) ? l0 * __expf(m0 - M) : 0.f)
                + ((m1 > -1e29f) ? l1 * __expf(m1 - M) : 0.f);
        g_ml[chunk][b][j0 + tid] = make_float2(M, L);
    }
}

// =========================== k_combine ===========================
__global__ void k_combine()
{
    int idx = blockIdx.x * 256 + threadIdx.x;
    if (idx >= BB * SEQ) return;
    int b = idx >> 12, j = idx & (SEQ - 1);
    int jt = j >> 7;
    int nc = (NQT - 1 - jt) / SC_QCHUNK + 1;
    float M = -1e30f;
    for (int c = 0; c < nc; c++) M = fmaxf(M, g_ml[c][b][j].x);
    float L = 0.f;
    for (int c = 0; c < nc; c++) {
        float2 p = g_ml[c][b][j];
        L += (p.x > -1e29f) ? p.y * __expf(p.x - M) : 0.f;
    }
    g_c[b][j] = M + logf(L);
}

// =========================== k_out (mma.sync bf16, P@V) ===========================
// smem: P/V tiles [128][136] bf16 hi/lo
#define KOS_PH 0
#define KOS_PL 34816
#define KOS_VH 69632
#define KOS_VL 104448
#define SM_KO  139264

__global__ __launch_bounds__(256, 1) void k_out()
{
    extern __shared__ char smc[];
    __nv_bfloat16* Ph = (__nv_bfloat16*)(smc + KOS_PH);
    __nv_bfloat16* Pl = (__nv_bfloat16*)(smc + KOS_PL);
    __nv_bfloat16* Vh = (__nv_bfloat16*)(smc + KOS_VH);
    __nv_bfloat16* Vl = (__nv_bfloat16*)(smc + KOS_VL);

    const int tid = threadIdx.x, lane = tid & 31, w = tid >> 5;
    const int r4 = lane >> 2, c2 = (lane & 3) * 2;
    const int qw = (w & 3) * 32, vw = (w >> 2) * 64;
    const int qt = blockIdx.x, chunk = blockIdx.y, b = blockIdx.z;
    int jt0 = chunk * OUT_JCHUNK;
    if (jt0 > qt) return;
    int jt1 = min(jt0 + OUT_JCHUNK - 1, qt);
    const int q0 = qt * 128;

    float acc[2][8][4];
    #pragma unroll
    for (int mt = 0; mt < 2; mt++)
        #pragma unroll
        for (int nt = 0; nt < 8; nt++)
            #pragma unroll
            for (int e = 0; e < 4; e++) acc[mt][nt][e] = 0.f;

    const int rr = tid >> 1, hf = tid & 1;
    for (int jt = jt0; jt <= jt1; jt++) {
        const int j0 = jt * 128;
        __syncthreads();
        {   // V tiles: g_Vt[b][v][s] -> Vs[v][jloc]
            const uint4* vh = (const uint4*)&g_Vthi[((size_t)(b * VD + rr)) * SEQ + j0 + hf * 64];
            const uint4* vl = (const uint4*)&g_Vtlo[((size_t)(b * VD + rr)) * SEQ + j0 + hf * 64];
            #pragma unroll
            for (int i = 0; i < 8; i++) {
                *(uint4*)&Vh[rr * 136 + hf * 64 + i * 8] = vh[i];
                *(uint4*)&Vl[rr * 136 + hf * 64 + i * 8] = vl[i];
            }
        }
        {   // P tiles: exp(S - c_j) split hi/lo
            const float* srow = &g_S[((size_t)(b * SEQ + q0 + rr)) * SEQ + j0 + hf * 64];
            const float* crow = &g_c[b][j0 + hf * 64];
            #pragma unroll
            for (int i = 0; i < 8; i++) {
                float4 sa = ((const float4*)srow)[i * 2];
                float4 sb = ((const float4*)srow)[i * 2 + 1];
                uint32_t hw[4], lw[4];
                split_pack(__expf(sa.x - crow[i*8+0]), __expf(sa.y - crow[i*8+1]), hw[0], lw[0]);
                split_pack(__expf(sa.z - crow[i*8+2]), __expf(sa.w - crow[i*8+3]), hw[1], lw[1]);
                split_pack(__expf(sb.x - crow[i*8+4]), __expf(sb.y - crow[i*8+5]), hw[2], lw[2]);
                split_pack(__expf(sb.z - crow[i*8+6]), __expf(sb.w - crow[i*8+7]), hw[3], lw[3]);
                *(uint4*)&Ph[rr * 136 + hf * 64 + i * 8] = make_uint4(hw[0], hw[1], hw[2], hw[3]);
                *(uint4*)&Pl[rr * 136 + hf * 64 + i * 8] = make_uint4(lw[0], lw[1], lw[2], lw[3]);
            }
        }
        __syncthreads();

        #pragma unroll
        for (int ks = 0; ks < 8; ks++) {
            const int col = ks * 16 + c2;
            uint32_t bh[8][2], bl[8][2];
            #pragma unroll
            for (int nt = 0; nt < 8; nt++) {
                int n = (vw + nt * 8 + r4) * 136 + col;
                bh[nt][0] = *(uint32_t*)&Vh[n]; bh[nt][1] = *(uint32_t*)&Vh[n + 8];
                bl[nt][0] = *(uint32_t*)&Vl[n]; bl[nt][1] = *(uint32_t*)&Vl[n + 8];
            }
            #pragma unroll
            for (int mt = 0; mt < 2; mt++) {
                int ra = (qw + mt * 16 + r4) * 136 + col;
                uint32_t ah[4], al[4];
                ah[0] = *(uint32_t*)&Ph[ra];     ah[1] = *(uint32_t*)&Ph[ra + 8 * 136];
                ah[2] = *(uint32_t*)&Ph[ra + 8]; ah[3] = *(uint32_t*)&Ph[ra + 8 * 136 + 8];
                al[0] = *(uint32_t*)&Pl[ra];     al[1] = *(uint32_t*)&Pl[ra + 8 * 136];
                al[2] = *(uint32_t*)&Pl[ra + 8]; al[3] = *(uint32_t*)&Pl[ra + 8 * 136 + 8];
                #pragma unroll
                for (int nt = 0; nt < 8; nt++) {
                    mma16816(acc[mt][nt], ah, bh[nt]);
                    mma16816(acc[mt][nt], ah, bl[nt]);
                    mma16816(acc[mt][nt], al, bh[nt]);
                }
            }
        }
    }
    // write deterministic partials
    #pragma unroll
    for (int mt = 0; mt < 2; mt++)
        #pragma unroll
        for (int nt = 0; nt < 8; nt++) {
            int vl_ = vw + nt * 8 + c2;
            #pragma unroll
            for (int half = 0; half < 2; half++) {
                int ql = qw + mt * 16 + r4 + half * 8;
                *(float2*)&g_Opart[chunk][b][q0 + ql][vl_] =
                    make_float2(acc[mt][nt][half * 2], acc[mt][nt][half * 2 + 1]);
            }
        }
}

// =========================== k_reduce (sum partials + concat x) ===========================
__global__ void k_reduce(const float* __restrict__ x, float* __restrict__ out)
{
    int idx = blockIdx.x * 256 + threadIdx.x;
    if (idx >= BB * SEQ * 64) return;
    int c4 = (idx & 63) * 4;
    int row = idx >> 6;
    int s = row & (SEQ - 1);
    int b = row >> 12;
    float4 v;
    if (c4 < 128) {
        v = *(const float4*)&x[(size_t)row * 128 + c4];
    } else {
        int vc = c4 - 128;
        int nc = (s >> 7) / OUT_JCHUNK + 1;
        v = make_float4(0.f, 0.f, 0.f, 0.f);
        for (int c = 0; c < nc; c++) {
            float4 p = *(const float4*)&g_Opart[c][b][s][vc];
            v.x += p.x; v.y += p.y; v.z += p.z; v.w += p.w;
        }
    }
    *(float4*)&out[(size_t)row * 256 + c4] = v;
}

// =========================== launch ===========================
extern "C" void kernel_launch(void* const* d_in, const int* in_sizes, int n_in,
                              void* d_out, int out_size)
{
    const float* x  = (const float*)d_in[0];
    const float* Wq = (const float*)d_in[1];
    const float* bq = (const float*)d_in[2];
    const float* Wk = (const float*)d_in[3];
    const float* bk = (const float*)d_in[4];
    const float* Wv = (const float*)d_in[5];
    const float* bv = (const float*)d_in[6];
    float* out = (float*)d_out;

    const int SM_PROJ = (128 * 133 * 2) * 4;

    cudaFuncSetAttribute(k_proj,   cudaFuncAttributeMaxDynamicSharedMemorySize, SM_PROJ);
    cudaFuncSetAttribute(k_scores, cudaFuncAttributeMaxDynamicSharedMemorySize, SM_SC);
    cudaFuncSetAttribute(k_out,    cudaFuncAttributeMaxDynamicSharedMemorySize, SM_KO);

    k_proj<<<dim3(128, 2), 256, SM_PROJ>>>(x, Wq, bq, Wk, bk, Wv, bv);
    k_scores<<<dim3(NJT, N_SCHUNK, BB), 256, SM_SC>>>();
    k_combine<<<(BB * SEQ + 255) / 256, 256>>>();
    k_out<<<dim3(NQT, N_OCHUNK, BB), 256, SM_KO>>>();
    k_reduce<<<(BB * SEQ * 64 + 255) / 256, 256>>>(x, out);
}